// round 4
// baseline (speedup 1.0000x reference)
#include <cuda_runtime.h>
#include <cuda_bf16.h>
#include <cstdint>

#define NN 100000
#define NE 1600000
#define HD 128
#define VC 1000
#define NT 782              // ceil(100000/128) M-tiles
#define MROWS (NT * 128)    // 100096 padded rows
#define NSB 98              // scan blocks

// ---------------- scratch (device globals; no allocation allowed) ----------
__device__ float g_h[NN * HD];          // current fp32 features (gather source)
__device__ int   g_cnt[NN];
__device__ int   g_off[NN + 1];
__device__ int   g_cur[NN];
__device__ int   g_srcs[NE];
__device__ int   g_fcarry[NSB];
__device__ int   g_fready[NSB];

// bf16 hi/lo operand buffers (row-major K-major)
__device__ __nv_bfloat16 g_Ahi[MROWS * 256];     // layer A = [mean | h], K=256
__device__ __nv_bfloat16 g_Alo[MROWS * 256];
__device__ __nv_bfloat16 g_FAhi[MROWS * 128];    // final A = h3, K=128
__device__ __nv_bfloat16 g_FAlo[MROWS * 128];
__device__ __nv_bfloat16 g_BthiL[3 * 128 * 256]; // layer Bt[l][n][k]
__device__ __nv_bfloat16 g_BtloL[3 * 128 * 256];
__device__ __nv_bfloat16 g_BthiF[1024 * 128];    // final Bt[n][k] = Wlast[k][n]
__device__ __nv_bfloat16 g_BtloF[1024 * 128];

// ---------------- helpers ------------------------------------------------------
__device__ __forceinline__ void split_pair(float v0, float v1, uint32_t& hi, uint32_t& lo) {
    __nv_bfloat16 h0 = __float2bfloat16(v0);
    __nv_bfloat16 h1 = __float2bfloat16(v1);
    __nv_bfloat16 l0 = __float2bfloat16(v0 - __bfloat162float(h0));
    __nv_bfloat16 l1 = __float2bfloat16(v1 - __bfloat162float(h1));
    __nv_bfloat162 hp = __nv_bfloat162(h0, h1);
    __nv_bfloat162 lp = __nv_bfloat162(l0, l1);
    hi = *(uint32_t*)&hp;
    lo = *(uint32_t*)&lp;
}

// ---------------- weight conversion (all layers + final, one launch) -----------
__global__ void k_convW(const float* __restrict__ Wl, const float* __restrict__ Wr,
                        const float* __restrict__ Wlast) {
    int idx = blockIdx.x * blockDim.x + threadIdx.x;
    if (idx < 3 * 128 * 128) {           // layer Bt: l, n(128), kp(128 u32-pairs of K=256)
        int l = idx >> 14, rem = idx & 16383;
        int n = rem >> 7, kp = rem & 127;
        int k = kp * 2;
        const float* WL = Wl + l * HD * HD;
        const float* WR = Wr + l * HD * HD;
        float v0 = (k < HD) ? WL[k * HD + n] : WR[(k - HD) * HD + n];
        float v1 = (k + 1 < HD) ? WL[(k + 1) * HD + n] : WR[(k + 1 - HD) * HD + n];
        uint32_t hi, lo;
        split_pair(v0, v1, hi, lo);
        ((uint32_t*)g_BthiL)[l * 16384 + n * 128 + kp] = hi;
        ((uint32_t*)g_BtloL)[l * 16384 + n * 128 + kp] = lo;
    } else if (idx < 3 * 128 * 128 + 1024 * 64) {   // final Bt: n(1024), kp(64)
        int j = idx - 49152;
        int n = j >> 6, kp = j & 63;
        int k = kp * 2;
        float v0 = 0.f, v1 = 0.f;
        if (n < VC) { v0 = Wlast[k * VC + n]; v1 = Wlast[(k + 1) * VC + n]; }
        uint32_t hi, lo;
        split_pair(v0, v1, hi, lo);
        ((uint32_t*)g_BthiF)[n * 64 + kp] = hi;
        ((uint32_t*)g_BtloF)[n * 64 + kp] = lo;
    }
}

// ---------------- embedding gather: h fp32 + A2 hi/lo ---------------------------
__global__ void k_embed(const int* __restrict__ x, const float* __restrict__ emb) {
    int i = blockIdx.x * blockDim.x + threadIdx.x;
    if (i >= NN * 32) return;
    int n = i >> 5, c = i & 31;
    float4 v = ((const float4*)emb)[x[n] * 32 + c];
    ((float4*)g_h)[i] = v;
    uint32_t hi0, lo0, hi1, lo1;
    split_pair(v.x, v.y, hi0, lo0);
    split_pair(v.z, v.w, hi1, lo1);
    ((uint2*)g_Ahi)[n * 64 + 32 + c] = make_uint2(hi0, hi1);
    ((uint2*)g_Alo)[n * 64 + 32 + c] = make_uint2(lo0, lo1);
}

// ---------------- CSR build ------------------------------------------------------
__global__ void k_hist(const int* __restrict__ dst) {
    int e = blockIdx.x * blockDim.x + threadIdx.x;
    if (e < NE) atomicAdd(&g_cnt[dst[e]], 1);
}

// single-kernel chained-carry scan: 98 blocks of 1024 (all co-resident)
__global__ void k_scanC() {
    __shared__ int s[1024];
    __shared__ int carry_s;
    int b = blockIdx.x;
    int i = b * 1024 + threadIdx.x;
    int v = (i < NN) ? g_cnt[i] : 0;
    s[threadIdx.x] = v;
    __syncthreads();
    for (int o = 1; o < 1024; o <<= 1) {
        int t = (threadIdx.x >= o) ? s[threadIdx.x - o] : 0;
        __syncthreads();
        s[threadIdx.x] += t;
        __syncthreads();
    }
    if (threadIdx.x == 0) {
        int carry = 0;
        if (b > 0) {
            volatile int* f = &g_fready[b - 1];
            while (*f == 0) {}
            carry = g_fcarry[b - 1];
        }
        g_fcarry[b] = carry + s[1023];
        __threadfence();
        g_fready[b] = 1;
        carry_s = carry;
    }
    __syncthreads();
    if (i < NN) g_off[i] = s[threadIdx.x] - v + carry_s;
    if (i == 0) g_off[NN] = NE;
}

__global__ void k_scatter(const int* __restrict__ src, const int* __restrict__ dst) {
    int e = blockIdx.x * blockDim.x + threadIdx.x;
    if (e < NE) {
        int d = dst[e];
        int p = g_off[d] + atomicAdd(&g_cur[d], 1);
        g_srcs[p] = src[e];
    }
}

// ---------------- mean aggregation: one warp per node, writes A1 hi/lo ----------
__global__ void k_agg() {
    int w = (blockIdx.x * blockDim.x + threadIdx.x) >> 5;
    int lane = threadIdx.x & 31;
    if (w >= NN) return;
    int beg = g_off[w], end = g_off[w + 1];
    float4 acc = make_float4(0.f, 0.f, 0.f, 0.f);
    const float4* h4 = (const float4*)g_h;
    for (int i = beg; i < end; i++) {
        int s = g_srcs[i];
        float4 v = h4[s * 32 + lane];
        acc.x += v.x; acc.y += v.y; acc.z += v.z; acc.w += v.w;
    }
    float inv = 1.0f / fmaxf((float)(end - beg), 1.0f);
    acc.x *= inv; acc.y *= inv; acc.z *= inv; acc.w *= inv;
    uint32_t hi0, lo0, hi1, lo1;
    split_pair(acc.x, acc.y, hi0, lo0);
    split_pair(acc.z, acc.w, hi1, lo1);
    ((uint2*)g_Ahi)[w * 64 + lane] = make_uint2(hi0, hi1);
    ((uint2*)g_Alo)[w * 64 + lane] = make_uint2(lo0, lo1);
}

// ---------------- mma.sync GEMM core --------------------------------------------
#define MMA4(c, a, b0, b1) \
    asm volatile("mma.sync.aligned.m16n8k16.row.col.f32.bf16.bf16.f32 " \
        "{%0,%1,%2,%3}, {%4,%5,%6,%7}, {%8,%9}, {%0,%1,%2,%3};" \
        : "+f"((c)[0]), "+f"((c)[1]), "+f"((c)[2]), "+f"((c)[3]) \
        : "r"((a)[0]), "r"((a)[1]), "r"((a)[2]), "r"((a)[3]), "r"(b0), "r"(b1))

#define GSMEM 73728    // 4 x 128 x 72 bf16
#define FSMEM 147456   // 4 x 128 x 144 bf16

// layer GEMM: A[K=256] x Bt(layer l), bias+relu.
// EPI 0: write g_h fp32 + A2 hi/lo (next layer); EPI 1: write FA hi/lo (final A).
template<int EPI>
__global__ void __launch_bounds__(256) k_mma_layer(int l, const float* __restrict__ bias) {
    extern __shared__ __align__(16) char smem[];
    __nv_bfloat16* sAhi = (__nv_bfloat16*)(smem);
    __nv_bfloat16* sAlo = (__nv_bfloat16*)(smem + 18432);
    __nv_bfloat16* sBhi = (__nv_bfloat16*)(smem + 36864);
    __nv_bfloat16* sBlo = (__nv_bfloat16*)(smem + 55296);
    const __nv_bfloat16* Bthi = g_BthiL + l * 32768;
    const __nv_bfloat16* Btlo = g_BtloL + l * 32768;

    int tid = threadIdx.x;
    int lane = tid & 31, wid = tid >> 5;
    int wm = wid & 3, wn = wid >> 2;
    int mbase = blockIdx.x * 128;

    float acc[2][8][4];
    #pragma unroll
    for (int i = 0; i < 2; i++)
        #pragma unroll
        for (int j = 0; j < 8; j++)
            #pragma unroll
            for (int q = 0; q < 4; q++) acc[i][j][q] = 0.f;

    for (int kc = 0; kc < 256; kc += 64) {
        __syncthreads();
        #pragma unroll
        for (int i = tid; i < 2048; i += 256) {
            int r = i >> 4, kq = i & 15;
            size_t ga = (size_t)(mbase + r) * 256 + kc + kq * 4;
            size_t gb = (size_t)r * 256 + kc + kq * 4;
            int so = r * 72 + kq * 4;
            *(uint2*)&sAhi[so] = *(const uint2*)&g_Ahi[ga];
            *(uint2*)&sAlo[so] = *(const uint2*)&g_Alo[ga];
            *(uint2*)&sBhi[so] = *(const uint2*)&Bthi[gb];
            *(uint2*)&sBlo[so] = *(const uint2*)&Btlo[gb];
        }
        __syncthreads();

        #pragma unroll
        for (int ks = 0; ks < 4; ks++) {
            int k0 = ks * 16;
            uint32_t ah[2][4], al[2][4];
            #pragma unroll
            for (int mi = 0; mi < 2; mi++) {
                int r0 = wm * 32 + mi * 16 + (lane >> 2);
                int c0 = k0 + (lane & 3) * 2;
                ah[mi][0] = *(uint32_t*)&sAhi[r0 * 72 + c0];
                ah[mi][1] = *(uint32_t*)&sAhi[(r0 + 8) * 72 + c0];
                ah[mi][2] = *(uint32_t*)&sAhi[r0 * 72 + c0 + 8];
                ah[mi][3] = *(uint32_t*)&sAhi[(r0 + 8) * 72 + c0 + 8];
                al[mi][0] = *(uint32_t*)&sAlo[r0 * 72 + c0];
                al[mi][1] = *(uint32_t*)&sAlo[(r0 + 8) * 72 + c0];
                al[mi][2] = *(uint32_t*)&sAlo[r0 * 72 + c0 + 8];
                al[mi][3] = *(uint32_t*)&sAlo[(r0 + 8) * 72 + c0 + 8];
            }
            #pragma unroll
            for (int nj = 0; nj < 8; nj++) {
                int nr = wn * 64 + nj * 8 + (lane >> 2);
                int ck = k0 + (lane & 3) * 2;
                uint32_t bh0 = *(uint32_t*)&sBhi[nr * 72 + ck];
                uint32_t bh1 = *(uint32_t*)&sBhi[nr * 72 + ck + 8];
                uint32_t bl0 = *(uint32_t*)&sBlo[nr * 72 + ck];
                uint32_t bl1 = *(uint32_t*)&sBlo[nr * 72 + ck + 8];
                #pragma unroll
                for (int mi = 0; mi < 2; mi++) {
                    MMA4(acc[mi][nj], ah[mi], bh0, bh1);
                    MMA4(acc[mi][nj], ah[mi], bl0, bl1);
                    MMA4(acc[mi][nj], al[mi], bh0, bh1);
                }
            }
        }
    }

    // epilogue: bias + relu, then route per EPI
    #pragma unroll
    for (int mi = 0; mi < 2; mi++) {
        int r0 = mbase + wm * 32 + mi * 16 + (lane >> 2);
        #pragma unroll
        for (int nj = 0; nj < 8; nj++) {
            int col = wn * 64 + nj * 8 + (lane & 3) * 2;
            float2 bb = *(const float2*)&bias[col];
            float v0 = fmaxf(acc[mi][nj][0] + bb.x, 0.f);
            float v1 = fmaxf(acc[mi][nj][1] + bb.y, 0.f);
            float v2 = fmaxf(acc[mi][nj][2] + bb.x, 0.f);
            float v3 = fmaxf(acc[mi][nj][3] + bb.y, 0.f);
            uint32_t hi, lo;
            if (r0 < NN) {
                split_pair(v0, v1, hi, lo);
                if (EPI == 0) {
                    *(float2*)&g_h[(size_t)r0 * HD + col] = make_float2(v0, v1);
                    ((uint32_t*)g_Ahi)[r0 * 128 + 64 + (col >> 1)] = hi;
                    ((uint32_t*)g_Alo)[r0 * 128 + 64 + (col >> 1)] = lo;
                } else {
                    ((uint32_t*)g_FAhi)[r0 * 64 + (col >> 1)] = hi;
                    ((uint32_t*)g_FAlo)[r0 * 64 + (col >> 1)] = lo;
                }
            }
            if (r0 + 8 < NN) {
                split_pair(v2, v3, hi, lo);
                if (EPI == 0) {
                    *(float2*)&g_h[(size_t)(r0 + 8) * HD + col] = make_float2(v2, v3);
                    ((uint32_t*)g_Ahi)[(r0 + 8) * 128 + 64 + (col >> 1)] = hi;
                    ((uint32_t*)g_Alo)[(r0 + 8) * 128 + 64 + (col >> 1)] = lo;
                } else {
                    ((uint32_t*)g_FAhi)[(r0 + 8) * 64 + (col >> 1)] = hi;
                    ((uint32_t*)g_FAlo)[(r0 + 8) * 64 + (col >> 1)] = lo;
                }
            }
        }
    }
}

// final GEMM: A (K=128) resident in SMEM, loop 8 N-tiles of Bt.
__global__ void __launch_bounds__(256, 1) k_mma_final(const float* __restrict__ blast,
                                                      float* __restrict__ out) {
    extern __shared__ __align__(16) char smem[];
    __nv_bfloat16* sAhi = (__nv_bfloat16*)(smem);
    __nv_bfloat16* sAlo = (__nv_bfloat16*)(smem + 36864);
    __nv_bfloat16* sBhi = (__nv_bfloat16*)(smem + 73728);
    __nv_bfloat16* sBlo = (__nv_bfloat16*)(smem + 110592);

    int tid = threadIdx.x;
    int lane = tid & 31, wid = tid >> 5;
    int wm = wid & 3, wn = wid >> 2;
    int mbase = blockIdx.x * 128;

    // load full-K A tile once: rows x 144 (two 64-chunks padded to 72)
    #pragma unroll
    for (int i = tid; i < 4096; i += 256) {
        int r = i >> 5, kq = i & 31;
        int so = r * 144 + (kq >> 4) * 72 + (kq & 15) * 4;
        size_t ga = (size_t)(mbase + r) * 128 + kq * 4;
        *(uint2*)&sAhi[so] = *(const uint2*)&g_FAhi[ga];
        *(uint2*)&sAlo[so] = *(const uint2*)&g_FAlo[ga];
    }

    for (int nt = 0; nt < 8; nt++) {
        __syncthreads();
        #pragma unroll
        for (int i = tid; i < 4096; i += 256) {
            int r = i >> 5, kq = i & 31;
            int so = r * 144 + (kq >> 4) * 72 + (kq & 15) * 4;
            size_t gb = (size_t)(nt * 128 + r) * 128 + kq * 4;
            *(uint2*)&sBhi[so] = *(const uint2*)&g_BthiF[gb];
            *(uint2*)&sBlo[so] = *(const uint2*)&g_BtloF[gb];
        }
        __syncthreads();

        float acc[2][8][4];
        #pragma unroll
        for (int i = 0; i < 2; i++)
            #pragma unroll
            for (int j = 0; j < 8; j++)
                #pragma unroll
                for (int q = 0; q < 4; q++) acc[i][j][q] = 0.f;

        #pragma unroll
        for (int kc = 0; kc < 2; kc++) {
            #pragma unroll
            for (int ks = 0; ks < 4; ks++) {
                int k0 = kc * 72 + ks * 16;
                uint32_t ah[2][4], al[2][4];
                #pragma unroll
                for (int mi = 0; mi < 2; mi++) {
                    int r0 = wm * 32 + mi * 16 + (lane >> 2);
                    int c0 = k0 + (lane & 3) * 2;
                    ah[mi][0] = *(uint32_t*)&sAhi[r0 * 144 + c0];
                    ah[mi][1] = *(uint32_t*)&sAhi[(r0 + 8) * 144 + c0];
                    ah[mi][2] = *(uint32_t*)&sAhi[r0 * 144 + c0 + 8];
                    ah[mi][3] = *(uint32_t*)&sAhi[(r0 + 8) * 144 + c0 + 8];
                    al[mi][0] = *(uint32_t*)&sAlo[r0 * 144 + c0];
                    al[mi][1] = *(uint32_t*)&sAlo[(r0 + 8) * 144 + c0];
                    al[mi][2] = *(uint32_t*)&sAlo[r0 * 144 + c0 + 8];
                    al[mi][3] = *(uint32_t*)&sAlo[(r0 + 8) * 144 + c0 + 8];
                }
                #pragma unroll
                for (int nj = 0; nj < 8; nj++) {
                    int nr = wn * 64 + nj * 8 + (lane >> 2);
                    int ck = k0 + (lane & 3) * 2;
                    uint32_t bh0 = *(uint32_t*)&sBhi[nr * 144 + ck];
                    uint32_t bh1 = *(uint32_t*)&sBhi[nr * 144 + ck + 8];
                    uint32_t bl0 = *(uint32_t*)&sBlo[nr * 144 + ck];
                    uint32_t bl1 = *(uint32_t*)&sBlo[nr * 144 + ck + 8];
                    #pragma unroll
                    for (int mi = 0; mi < 2; mi++) {
                        MMA4(acc[mi][nj], ah[mi], bh0, bh1);
                        MMA4(acc[mi][nj], ah[mi], bl0, bl1);
                        MMA4(acc[mi][nj], al[mi], bh0, bh1);
                    }
                }
            }
        }

        // epilogue for this N-tile
        #pragma unroll
        for (int mi = 0; mi < 2; mi++) {
            int r0 = mbase + wm * 32 + mi * 16 + (lane >> 2);
            #pragma unroll
            for (int nj = 0; nj < 8; nj++) {
                int col = nt * 128 + wn * 64 + nj * 8 + (lane & 3) * 2;
                if (col < VC) {
                    float2 bb = *(const float2*)&blast[col];
                    if (r0 < NN)
                        *(float2*)&out[(size_t)r0 * VC + col] =
                            make_float2(acc[mi][nj][0] + bb.x, acc[mi][nj][1] + bb.y);
                    if (r0 + 8 < NN)
                        *(float2*)&out[(size_t)(r0 + 8) * VC + col] =
                            make_float2(acc[mi][nj][2] + bb.x, acc[mi][nj][3] + bb.y);
                }
            }
        }
        __syncthreads();
    }
}

// ---------------- softmax: one warp per node, float4 ---------------------------
__global__ void k_softmax(float* __restrict__ out) {
    int w = (blockIdx.x * blockDim.x + threadIdx.x) >> 5;
    int lane = threadIdx.x & 31;
    if (w >= NN) return;
    float4* row = (float4*)(out + (size_t)w * VC);
    float4 v[8];
    float m = -1e30f;
    #pragma unroll
    for (int i = 0; i < 8; i++) {
        int idx = lane + i * 32;
        if (idx < 250) {
            v[i] = row[idx];
            m = fmaxf(m, fmaxf(fmaxf(v[i].x, v[i].y), fmaxf(v[i].z, v[i].w)));
        } else {
            v[i] = make_float4(-1e30f, -1e30f, -1e30f, -1e30f);
        }
    }
    #pragma unroll
    for (int o = 16; o; o >>= 1) m = fmaxf(m, __shfl_xor_sync(0xffffffffu, m, o));
    float s = 0.f;
    #pragma unroll
    for (int i = 0; i < 8; i++) {
        v[i].x = __expf(v[i].x - m); v[i].y = __expf(v[i].y - m);
        v[i].z = __expf(v[i].z - m); v[i].w = __expf(v[i].w - m);
        s += v[i].x + v[i].y + v[i].z + v[i].w;
    }
    #pragma unroll
    for (int o = 16; o; o >>= 1) s += __shfl_xor_sync(0xffffffffu, s, o);
    float inv = 1.0f / s;
    #pragma unroll
    for (int i = 0; i < 8; i++) {
        int idx = lane + i * 32;
        if (idx < 250) {
            v[i].x *= inv; v[i].y *= inv; v[i].z *= inv; v[i].w *= inv;
            row[idx] = v[i];
        }
    }
}

// ---------------- launch ---------------------------------------------------------
extern "C" void kernel_launch(void* const* d_in, const int* in_sizes, int n_in,
                              void* d_out, int out_size) {
    const int*   x     = (const int*)d_in[0];
    const int*   ei    = (const int*)d_in[1];
    const int*   src   = ei;
    const int*   dst   = ei + NE;
    const float* emb   = (const float*)d_in[2];
    const float* Wl    = (const float*)d_in[3];
    const float* bl    = (const float*)d_in[4];
    const float* Wr    = (const float*)d_in[5];
    const float* Wlast = (const float*)d_in[6];
    const float* blast = (const float*)d_in[7];
    float* out = (float*)d_out;

    cudaFuncSetAttribute(k_mma_layer<0>, cudaFuncAttributeMaxDynamicSharedMemorySize, GSMEM);
    cudaFuncSetAttribute(k_mma_layer<1>, cudaFuncAttributeMaxDynamicSharedMemorySize, GSMEM);
    cudaFuncSetAttribute(k_mma_final, cudaFuncAttributeMaxDynamicSharedMemorySize, FSMEM);

    void *pcnt, *pcur, *pready;
    cudaGetSymbolAddress(&pcnt, g_cnt);
    cudaGetSymbolAddress(&pcur, g_cur);
    cudaGetSymbolAddress(&pready, g_fready);
    cudaMemsetAsync(pcnt, 0, NN * sizeof(int));
    cudaMemsetAsync(pcur, 0, NN * sizeof(int));
    cudaMemsetAsync(pready, 0, NSB * sizeof(int));

    k_convW<<<(3 * 16384 + 1024 * 64 + 255) / 256, 256>>>(Wl, Wr, Wlast);
    k_embed<<<(NN * 32 + 255) / 256, 256>>>(x, emb);
    k_hist<<<(NE + 255) / 256, 256>>>(dst);
    k_scanC<<<NSB, 1024>>>();
    k_scatter<<<(NE + 255) / 256, 256>>>(src, dst);

    k_agg<<<(NN * 32 + 255) / 256, 256>>>();
    k_mma_layer<0><<<NT, 256, GSMEM>>>(0, bl + 0 * HD);
    k_agg<<<(NN * 32 + 255) / 256, 256>>>();
    k_mma_layer<0><<<NT, 256, GSMEM>>>(1, bl + 1 * HD);
    k_agg<<<(NN * 32 + 255) / 256, 256>>>();
    k_mma_layer<1><<<NT, 256, GSMEM>>>(2, bl + 2 * HD);

    k_mma_final<<<NT, 256, FSMEM>>>(blast, out);
    k_softmax<<<(NN * 32 + 255) / 256, 256>>>(out);
}